// round 16
// baseline (speedup 1.0000x reference)
#include <cuda_runtime.h>
#include <cuda_fp16.h>
#include <cstdint>

// Renderer_45612552684068 — round 15: MLP retiled to 256 px/block, 512 thr
// (2x weight-staging amortization, 16 warps). Convs unchanged from R14.

static constexpr int NB   = 4;
static constexpr int NH   = 512;
static constexpr int NW   = 512;
static constexpr int HID  = 128;
static constexpr int CIN  = 29;
static constexpr int C1C  = 64;
static constexpr int C2C  = 128;

__device__ __align__(16) float  g_rgb[NB * 3 * NH * NW];
__device__ __align__(16) __half g_xh [NB * NH * NW * 32];
__device__ __align__(16) __half g_e1h[NB * NH * NW * 64];
__device__ __align__(16) __half g_dh [NB * (NH/2) * (NW/2) * 128];
__device__ __align__(16) __half g_mh [NB * NH * NW * 64];

static constexpr int W1H_SZ = 9 * 64 * 40;
static constexpr int W2H_SZ = 4 * 9 * 128 * 24;
static constexpr int W3H_SZ = 6 * 9 * 64 * 40;
static constexpr int W4H_SZ = 4 * 9 * 8 * 24;
__device__ __align__(16) __half w1h[W1H_SZ];
__device__ __align__(16) __half w2h[W2H_SZ];
__device__ __align__(16) __half w3h[W3H_SZ];
__device__ __align__(16) __half w4h[W4H_SZ];
static constexpr int W1M_SZ = 128 * 136;
static constexpr int W2M_SZ = 32 * 136;
__device__ __align__(16) __half w1mh[W1M_SZ];
__device__ __align__(16) __half w2mh[W2M_SZ];

__device__ __forceinline__ void mma_f16(float c[4],
                                        uint32_t a0, uint32_t a1,
                                        uint32_t a2, uint32_t a3,
                                        uint32_t b0, uint32_t b1) {
    asm volatile(
        "mma.sync.aligned.m16n8k16.row.col.f32.f16.f16.f32 "
        "{%0,%1,%2,%3}, {%4,%5,%6,%7}, {%8,%9}, {%0,%1,%2,%3};"
        : "+f"(c[0]), "+f"(c[1]), "+f"(c[2]), "+f"(c[3])
        : "r"(a0), "r"(a1), "r"(a2), "r"(a3), "r"(b0), "r"(b1));
}

__device__ __forceinline__ void ldsm4(uint32_t& r0, uint32_t& r1,
                                      uint32_t& r2, uint32_t& r3,
                                      const __half* p) {
    uint32_t a = (uint32_t)__cvta_generic_to_shared(p);
    asm volatile("ldmatrix.sync.aligned.m8n8.x4.shared.b16 {%0,%1,%2,%3}, [%4];"
                 : "=r"(r0), "=r"(r1), "=r"(r2), "=r"(r3) : "r"(a));
}

__device__ __forceinline__ void cp_async16(__half* smem_dst, const void* gsrc) {
    uint32_t d = (uint32_t)__cvta_generic_to_shared(smem_dst);
    asm volatile("cp.async.cg.shared.global [%0], [%1], 16;" :: "r"(d), "l"(gsrc));
}
__device__ __forceinline__ void cp_async8z(__half* smem_dst, const void* gsrc, bool valid) {
    uint32_t d = (uint32_t)__cvta_generic_to_shared(smem_dst);
    int sz = valid ? 8 : 0;
    asm volatile("cp.async.ca.shared.global [%0], [%1], 8, %2;"
                 :: "r"(d), "l"(gsrc), "r"(sz));
}
__device__ __forceinline__ void cp_commit() {
    asm volatile("cp.async.commit_group;");
}
template <int N>
__device__ __forceinline__ void cp_wait() {
    asm volatile("cp.async.wait_group %0;" :: "n"(N));
}

// ---------------------------------------------------------------------------
__global__ void prep_weights(const float* __restrict__ k1, const float* __restrict__ k2,
                             const float* __restrict__ k3, const float* __restrict__ k4,
                             const float* __restrict__ mw1, const float* __restrict__ mw2)
{
    int i = blockIdx.x * 256 + threadIdx.x;
    if (i < W1H_SZ) {
        int tap = i / 2560, r = i % 2560, co = r / 40, k = r % 40;
        w1h[i] = __float2half(k < CIN ? k1[(co * CIN + k) * 9 + tap] : 0.f);
        return;
    }
    i -= W1H_SZ;
    if (i < W2H_SZ) {
        int c = i / 27648, r = i % 27648;
        int tap = r / 3072, co = (r % 3072) / 24, k = r % 24;
        w2h[i] = __float2half(k < 16 ? k2[(co * C1C + c * 16 + k) * 9 + tap] : 0.f);
        return;
    }
    i -= W2H_SZ;
    if (i < W3H_SZ) {
        int c = i / 23040, r = i % 23040;
        int tap = r / 2560, co = (r % 2560) / 40, k = r % 40;
        w3h[i] = __float2half(k < 32 ? k3[(co * (C2C + C1C) + c * 32 + k) * 9 + tap] : 0.f);
        return;
    }
    i -= W3H_SZ;
    if (i < W4H_SZ) {
        int c = i / 1728, r = i % 1728;
        int tap = r / 192, co = (r % 192) / 24, k = r % 24;
        w4h[i] = __float2half((k < 16 && co < 3) ? k4[(co * C1C + c * 16 + k) * 9 + tap] : 0.f);
        return;
    }
    i -= W4H_SZ;
    if (i < W1M_SZ) {
        int n = i / 136, k = i % 136;
        w1mh[i] = __float2half(k < HID ? mw1[k * HID + n] : 0.f);
        return;
    }
    i -= W1M_SZ;
    if (i < W2M_SZ) {
        int n = i / 136, k = i % 136;
        w2mh[i] = __float2half(k < HID ? mw2[k * 32 + n] : 0.f);
    }
}

// ---------------------------------------------------------------------------
// MLP: 256 px / block, 512 thr (16 warps). Layer0 fp32 scalar; layers 1/2
// fp16 mma via ldmatrix. Weight staging amortized over 2x pixels vs R14.
static constexpr int MLP_H1_OFF  = 0;        // half[256][136] = 69632
static constexpr int MLP_W1_OFF  = 69632;    // half[128][136] = 34816
static constexpr int MLP_W2_OFF  = 104448;   // half[32][136]  = 8704
static constexpr int MLP_W0_OFF  = 113152;   // float[6][128]  = 3072
static constexpr int MLP_FIN_OFF = 116224;   // float[256][8]  = 8192
static constexpr int MLP_Z_OFF   = 124416;   // float[256]     = 1024
static constexpr int MLP_B0_OFF  = 125440;   // float[128]     = 512
static constexpr int MLP_B1_OFF  = 125952;   // float[128]     = 512
static constexpr int MLP_B2_OFF  = 126464;   // float[32]      = 128
static constexpr int MLP_SMEM_BYTES = 126592;

__global__ __launch_bounds__(512, 1)
void mlp_kernel(const float* __restrict__ zbuf, const float* __restrict__ ray,
                const float* __restrict__ w0, const float* __restrict__ b0,
                const float* __restrict__ b1, const float* __restrict__ b2)
{
    extern __shared__ __align__(16) char msm[];
    __half* sh_h1 = (__half*)(msm + MLP_H1_OFF);
    __half* sh_w1 = (__half*)(msm + MLP_W1_OFF);
    __half* sh_w2 = (__half*)(msm + MLP_W2_OFF);
    float*  sh_w0 = (float*)(msm + MLP_W0_OFF);
    float*  sh_fin= (float*)(msm + MLP_FIN_OFF);
    float*  sh_z  = (float*)(msm + MLP_Z_OFF);
    float*  sh_b0 = (float*)(msm + MLP_B0_OFF);
    float*  sh_b1 = (float*)(msm + MLP_B1_OFF);
    float*  sh_b2 = (float*)(msm + MLP_B2_OFF);

    const int tid   = threadIdx.x;
    const int w     = tid >> 5;
    const int lane  = tid & 31;
    const int gid   = lane >> 2;
    const int tig   = lane & 3;
    const int aRow  = lane & 15;
    const int aCol  = (lane >> 4) * 8;
    const int bRow  = (lane & 7) + 8 * (lane >> 4);
    const int bCol  = 8 * ((lane >> 3) & 1);
    const int pbase = blockIdx.x * 256;

    {
        const uint4* s1 = (const uint4*)w1mh;
        uint4* d1 = (uint4*)sh_w1;
        for (int t = tid; t < W1M_SZ / 8; t += 512) d1[t] = s1[t];
        const uint4* s2 = (const uint4*)w2mh;
        uint4* d2 = (uint4*)sh_w2;
        for (int t = tid; t < W2M_SZ / 8; t += 512) d2[t] = s2[t];
        for (int t = tid; t < 768; t += 512) sh_w0[t] = w0[t];
        if (tid < 128) { sh_b0[tid] = b0[tid]; sh_b1[tid] = b1[tid]; }
        if (tid < 32)  sh_b2[tid] = b2[tid];
    }

    // fin for 256 px (threads 0..255)
    if (tid < 256) {
        int pix = pbase + tid;
        int b = pix >> 18;
        int y = (pix >> 9) & 511;
        int x = pix & 511;
        int pi = (b * NH + y) * NW + x;
        float z = zbuf[pi];
        const float* r = ray + pi * 7;
        float t  = z / r[6];
        float d0 = r[3], d1 = r[4], d2 = r[5];
        sh_fin[tid * 8 + 0] = fmaf(d0, t, r[0]);
        sh_fin[tid * 8 + 1] = fmaf(d1, t, r[1]);
        sh_fin[tid * 8 + 2] = fmaf(d2, t, r[2]);
        sh_fin[tid * 8 + 3] = d0;
        sh_fin[tid * 8 + 4] = d1;
        sh_fin[tid * 8 + 5] = d2;
        sh_z[tid] = z;
    }
    __syncthreads();

    // layer0: 512 thr, 2 thr per px, each does 64 of 128 outputs
    {
        const int p  = tid & 255;
        const int ob = (tid >> 8) * 64;
        float f0 = sh_fin[p*8+0], f1 = sh_fin[p*8+1], f2 = sh_fin[p*8+2];
        float f3 = sh_fin[p*8+3], f4 = sh_fin[p*8+4], f5 = sh_fin[p*8+5];
        #pragma unroll 8
        for (int o = ob; o < ob + 64; o += 2) {
            float a0 = sh_b0[o],     a1 = sh_b0[o+1];
            a0 = fmaf(f0, sh_w0[0*HID + o], a0);  a1 = fmaf(f0, sh_w0[0*HID + o+1], a1);
            a0 = fmaf(f1, sh_w0[1*HID + o], a0);  a1 = fmaf(f1, sh_w0[1*HID + o+1], a1);
            a0 = fmaf(f2, sh_w0[2*HID + o], a0);  a1 = fmaf(f2, sh_w0[2*HID + o+1], a1);
            a0 = fmaf(f3, sh_w0[3*HID + o], a0);  a1 = fmaf(f3, sh_w0[3*HID + o+1], a1);
            a0 = fmaf(f4, sh_w0[4*HID + o], a0);  a1 = fmaf(f4, sh_w0[4*HID + o+1], a1);
            a0 = fmaf(f5, sh_w0[5*HID + o], a0);  a1 = fmaf(f5, sh_w0[5*HID + o+1], a1);
            *(__half2*)(sh_h1 + p * 136 + o) =
                __floats2half2_rn(fmaxf(a0, 0.f), fmaxf(a1, 0.f));
        }
    }
    __syncthreads();

    // layer1: 16 warps = 8 m-tiles (32px) x 2 n-tiles (64n)
    const int mw = w & 7, nw = w >> 3;
    const int mbase = 32 * mw, nbase = 64 * nw;
    float c1[2][8][4];
    #pragma unroll
    for (int mt = 0; mt < 2; mt++)
        #pragma unroll
        for (int nt = 0; nt < 8; nt++)
            #pragma unroll
            for (int q = 0; q < 4; q++) c1[mt][nt][q] = 0.f;

    #pragma unroll
    for (int ks = 0; ks < 8; ks++) {
        const int kofs = 16 * ks;
        uint32_t a[2][4];
        #pragma unroll
        for (int mt = 0; mt < 2; mt++)
            ldsm4(a[mt][0], a[mt][1], a[mt][2], a[mt][3],
                  sh_h1 + (mbase + 16*mt + aRow) * 136 + kofs + aCol);
        #pragma unroll
        for (int p = 0; p < 4; p++) {
            uint32_t bb[4];
            ldsm4(bb[0], bb[1], bb[2], bb[3],
                  sh_w1 + (nbase + 16*p + bRow) * 136 + kofs + bCol);
            mma_f16(c1[0][2*p],   a[0][0], a[0][1], a[0][2], a[0][3], bb[0], bb[1]);
            mma_f16(c1[1][2*p],   a[1][0], a[1][1], a[1][2], a[1][3], bb[0], bb[1]);
            mma_f16(c1[0][2*p+1], a[0][0], a[0][1], a[0][2], a[0][3], bb[2], bb[3]);
            mma_f16(c1[1][2*p+1], a[1][0], a[1][1], a[1][2], a[1][3], bb[2], bb[3]);
        }
    }
    __syncthreads();

    #pragma unroll
    for (int nt = 0; nt < 8; nt++) {
        const int n0 = nbase + 8*nt + 2*tig;
        float bb0 = sh_b1[n0], bb1 = sh_b1[n0 + 1];
        #pragma unroll
        for (int mt = 0; mt < 2; mt++) {
            int p0 = mbase + 16*mt + gid;
            *(__half2*)(sh_h1 + p0 * 136 + n0) =
                __floats2half2_rn(fmaxf(c1[mt][nt][0] + bb0, 0.f),
                                  fmaxf(c1[mt][nt][1] + bb1, 0.f));
            *(__half2*)(sh_h1 + (p0 + 8) * 136 + n0) =
                __floats2half2_rn(fmaxf(c1[mt][nt][2] + bb0, 0.f),
                                  fmaxf(c1[mt][nt][3] + bb1, 0.f));
        }
    }
    __syncthreads();

    // layer2: 16 warps x 16 px, N=32
    float d2[4][4];
    #pragma unroll
    for (int nt = 0; nt < 4; nt++)
        #pragma unroll
        for (int q = 0; q < 4; q++) d2[nt][q] = 0.f;

    #pragma unroll
    for (int ks = 0; ks < 8; ks++) {
        const int kofs = 16 * ks;
        uint32_t a0, a1, a2, a3;
        ldsm4(a0, a1, a2, a3, sh_h1 + (16*w + aRow) * 136 + kofs + aCol);
        #pragma unroll
        for (int p = 0; p < 2; p++) {
            uint32_t bb[4];
            ldsm4(bb[0], bb[1], bb[2], bb[3],
                  sh_w2 + (16*p + bRow) * 136 + kofs + bCol);
            mma_f16(d2[2*p],   a0, a1, a2, a3, bb[0], bb[1]);
            mma_f16(d2[2*p+1], a0, a1, a2, a3, bb[2], bb[3]);
        }
    }

    #pragma unroll
    for (int nt = 0; nt < 4; nt++) {
        const int n0 = 8*nt + 2*tig;
        const float bb0 = sh_b2[n0], bb1 = sh_b2[n0 + 1];
        #pragma unroll
        for (int rr = 0; rr < 2; rr++) {
            const int p = 16*w + gid + 8*rr;
            const int pix = pbase + p;
            const bool mask = sh_z[p] > 0.f;
            float v0 = mask ? (d2[nt][2*rr]     + bb0) : 1.0f;
            float v1 = mask ? (d2[nt][2*rr + 1] + bb1) : 1.0f;
            float x0 = (n0     < CIN) ? v0 : 0.f;
            float x1 = (n0 + 1 < CIN) ? v1 : 0.f;
            *(__half2*)(g_xh + (size_t)pix * 32 + n0) = __floats2half2_rn(x0, x1);
            if (n0 + 1 >= CIN) {
                int b = pix >> 18;
                int y = (pix >> 9) & 511;
                int x = pix & 511;
                if (n0 >= CIN)
                    g_rgb[((b*3 + (n0 - CIN)) * NH + y) * NW + x] = v0;
                g_rgb[((b*3 + (n0 + 1 - CIN)) * NH + y) * NW + x] = v1;
            }
        }
    }
}

// ---------------------------------------------------------------------------
// conv13: double-buffered cp.async (unchanged from passing R14).
static constexpr int C13_BUF_HALVES = 612 * 40 + 9 * 64 * 40;   // 47520
static constexpr int C13_SMEM_BYTES = C13_BUF_HALVES * 2 * 2;   // 190080

__global__ __launch_bounds__(256, 1)
void conv13_kernel(int nchunks, int mode)
{
    extern __shared__ __half c13sm[];

    const int tid  = threadIdx.x;
    const int w    = tid >> 5;
    const int lane = tid & 31;
    const int gid  = lane >> 2;
    const int tig  = lane & 3;
    const int aRow = lane & 15;
    const int aCol = (lane >> 4) * 8;
    const int bRow = (lane & 7) + 8 * (lane >> 4);
    const int bCol = 8 * ((lane >> 3) & 1);

    const int x0 = blockIdx.x * 16, y0 = blockIdx.y * 32, b = blockIdx.z;

    const __half* wsrc = (mode == 0) ? w1h : w3h;

    auto stage = [&](int ch, int bsel) {
        __half* in_s = c13sm + bsel * C13_BUF_HALVES;
        __half* w_s  = in_s + 612 * 40;
        for (int t = tid; t < 612 * 8; t += 256) {
            int tpx = t >> 3, ci4 = t & 7;
            int yy = tpx / 18, xx = tpx - yy * 18;
            int iy = y0 - 1 + yy, ix = x0 - 1 + xx;
            bool valid = (iy >= 0 && iy < NH && ix >= 0 && ix < NW);
            const __half* src;
            if (mode == 0) {
                size_t pix = valid ? ((size_t)(b * NH + iy) * NW + ix) : 0;
                src = g_xh + pix * 32 + ci4 * 4;
            } else {
                int ci = ch * 32 + ci4 * 4;
                if (ci < C2C) {
                    size_t pixd = valid ? ((size_t)(b * (NH/2) + (iy >> 1)) * (NW/2) + (ix >> 1)) : 0;
                    src = g_dh + pixd * 128 + ci;
                } else {
                    size_t pix = valid ? ((size_t)(b * NH + iy) * NW + ix) : 0;
                    src = g_e1h + pix * 64 + (ci - C2C);
                }
            }
            cp_async8z(in_s + tpx * 40 + ci4 * 4, src, valid);
        }
        const __half* wsrc_ch = wsrc + ch * 23040;
        for (int t = tid; t < 2880; t += 256)
            cp_async16(w_s + t * 8, wsrc_ch + t * 8);
    };

    float c[4][8][4];
    #pragma unroll
    for (int mt = 0; mt < 4; mt++)
        #pragma unroll
        for (int nt = 0; nt < 8; nt++)
            #pragma unroll
            for (int q = 0; q < 4; q++) c[mt][nt][q] = 0.f;

    stage(0, 0);
    cp_commit();

    for (int ch = 0; ch < nchunks; ch++) {
        const int bsel = ch & 1;
        if (ch + 1 < nchunks) {
            stage(ch + 1, bsel ^ 1);
            cp_commit();
            cp_wait<1>();
        } else {
            cp_wait<0>();
        }
        __syncthreads();

        const __half* in_s = c13sm + bsel * C13_BUF_HALVES;
        const __half* w_s  = in_s + 612 * 40;

        #pragma unroll
        for (int tap = 0; tap < 9; tap++) {
            const int ky = tap / 3, kx = tap - 3 * (tap / 3);
            #pragma unroll
            for (int g = 0; g < 2; g++) {
                uint32_t bb[4][4];
                #pragma unroll
                for (int p = 0; p < 4; p++)
                    ldsm4(bb[p][0], bb[p][1], bb[p][2], bb[p][3],
                          w_s + (tap * 64 + 16*p + bRow) * 40 + 16*g + bCol);
                #pragma unroll
                for (int mt = 0; mt < 4; mt++) {
                    uint32_t a0, a1, a2, a3;
                    ldsm4(a0, a1, a2, a3,
                          in_s + ((4*w + mt + ky) * 18 + kx + aRow) * 40 + 16*g + aCol);
                    #pragma unroll
                    for (int p = 0; p < 4; p++) {
                        mma_f16(c[mt][2*p],   a0, a1, a2, a3, bb[p][0], bb[p][1]);
                        mma_f16(c[mt][2*p+1], a0, a1, a2, a3, bb[p][2], bb[p][3]);
                    }
                }
            }
        }
        __syncthreads();
    }

    __half* dst = (mode == 0) ? g_e1h : g_mh;
    #pragma unroll
    for (int mt = 0; mt < 4; mt++) {
        const int y = y0 + 4 * w + mt;
        #pragma unroll
        for (int nt = 0; nt < 8; nt++) {
            const int co = 8 * nt + 2 * tig;
            size_t p1 = ((size_t)(b * NH + y) * NW + x0 + gid) * 64 + co;
            size_t p2 = ((size_t)(b * NH + y) * NW + x0 + gid + 8) * 64 + co;
            *(__half2*)(dst + p1) = __floats2half2_rn(fmaxf(c[mt][nt][0], 0.f),
                                                      fmaxf(c[mt][nt][1], 0.f));
            *(__half2*)(dst + p2) = __floats2half2_rn(fmaxf(c[mt][nt][2], 0.f),
                                                      fmaxf(c[mt][nt][3], 0.f));
        }
    }
}

// ---------------------------------------------------------------------------
// conv2: double-buffered cp.async (unchanged from passing R14).
static constexpr int C2_BUF_HALVES = 1089 * 24 + 9 * 128 * 24;  // 53784
static constexpr int C2_SMEM_BYTES = C2_BUF_HALVES * 2 * 2;     // 215136

__global__ __launch_bounds__(512, 1)
void conv2_kernel()
{
    extern __shared__ __half c2sm[];

    const int tid  = threadIdx.x;
    const int w    = tid >> 5;
    const int lane = tid & 31;
    const int gid  = lane >> 2;
    const int tig  = lane & 3;
    const int aRow = lane & 15;
    const int aCol = (lane >> 4) * 8;
    const int bRow = (lane & 7) + 8 * (lane >> 4);
    const int bCol = 8 * ((lane >> 3) & 1);
    const int coh  = w >> 3;
    const int wy   = w & 7;

    const int x0 = blockIdx.x * 16, y0 = blockIdx.y * 16, b = blockIdx.z;

    auto stage = [&](int ch, int bsel) {
        __half* in_s = c2sm + bsel * C2_BUF_HALVES;
        __half* w_s  = in_s + 1089 * 24;
        for (int t = tid; t < 1089 * 4; t += 512) {
            int tpx = t >> 2, ci4 = t & 3;
            int yy = tpx / 33, xx = tpx - yy * 33;
            int iy = 2 * y0 + yy, ix = 2 * x0 + xx;     // pad_lo = 0
            int pos = yy * 33 + ((xx & 1) ? 17 + (xx >> 1) : (xx >> 1));
            bool valid = (iy < NH && ix < NW);
            size_t pix = valid ? ((size_t)(b * NH + iy) * NW + ix) : 0;
            const __half* src = g_e1h + pix * 64 + ch * 16 + ci4 * 4;
            cp_async8z(in_s + pos * 24 + ci4 * 4, src, valid);
        }
        const __half* wsrc_ch = w2h + ch * 27648;
        for (int t = tid; t < 3456; t += 512)
            cp_async16(w_s + t * 8, wsrc_ch + t * 8);
    };

    float c[2][8][4];
    #pragma unroll
    for (int mt = 0; mt < 2; mt++)
        #pragma unroll
        for (int nt = 0; nt < 8; nt++)
            #pragma unroll
            for (int q = 0; q < 4; q++) c[mt][nt][q] = 0.f;

    stage(0, 0);
    cp_commit();

    for (int ch = 0; ch < 4; ch++) {
        const int bsel = ch & 1;
        if (ch + 1 < 4) {
            stage(ch + 1, bsel ^ 1);
            cp_commit();
            cp_wait<1>();
        } else {
            cp_wait<0>();
        }
        __syncthreads();

        const __half* in_s = c2sm + bsel * C2_BUF_HALVES;
        const __half* w_s  = in_s + 1089 * 24;

        #pragma unroll
        for (int tap = 0; tap < 9; tap++) {
            const int ky = tap / 3, kx = tap - 3 * (tap / 3);
            const int colbase = (kx == 1) ? 17 : (kx >> 1);
            uint32_t a[2][4];
            #pragma unroll
            for (int mt = 0; mt < 2; mt++)
                ldsm4(a[mt][0], a[mt][1], a[mt][2], a[mt][3],
                      in_s + ((2*(2*wy + mt) + ky) * 33 + colbase + aRow) * 24 + aCol);
            #pragma unroll
            for (int p = 0; p < 4; p++) {
                uint32_t bb[4];
                ldsm4(bb[0], bb[1], bb[2], bb[3],
                      w_s + (tap * 128 + coh * 64 + 16*p + bRow) * 24 + bCol);
                mma_f16(c[0][2*p],   a[0][0], a[0][1], a[0][2], a[0][3], bb[0], bb[1]);
                mma_f16(c[1][2*p],   a[1][0], a[1][1], a[1][2], a[1][3], bb[0], bb[1]);
                mma_f16(c[0][2*p+1], a[0][0], a[0][1], a[0][2], a[0][3], bb[2], bb[3]);
                mma_f16(c[1][2*p+1], a[1][0], a[1][1], a[1][2], a[1][3], bb[2], bb[3]);
            }
        }
        __syncthreads();
    }

    #pragma unroll
    for (int mt = 0; mt < 2; mt++) {
        const int y = y0 + 2 * wy + mt;
        #pragma unroll
        for (int nt = 0; nt < 8; nt++) {
            const int co = coh * 64 + 8 * nt + 2 * tig;
            size_t p1 = ((size_t)(b * (NH/2) + y) * (NW/2) + x0 + gid) * 128 + co;
            size_t p2 = ((size_t)(b * (NH/2) + y) * (NW/2) + x0 + gid + 8) * 128 + co;
            *(__half2*)(g_dh + p1) = __floats2half2_rn(fmaxf(c[mt][nt][0], 0.f),
                                                       fmaxf(c[mt][nt][1], 0.f));
            *(__half2*)(g_dh + p2) = __floats2half2_rn(fmaxf(c[mt][nt][2], 0.f),
                                                       fmaxf(c[mt][nt][3], 0.f));
        }
    }
}

// ---------------------------------------------------------------------------
// conv4: double-buffered cp.async (unchanged from passing R14).
static constexpr int C4_BUF_HALVES = 324 * 24 + 9 * 8 * 24;     // 9504
static constexpr int C4_SMEM_BYTES = C4_BUF_HALVES * 2 * 2;     // 38016

__global__ __launch_bounds__(256)
void conv4_kernel(float* __restrict__ out)
{
    extern __shared__ __half c4sm[];

    const int tid  = threadIdx.x;
    const int w    = tid >> 5;
    const int lane = tid & 31;
    const int gid  = lane >> 2;
    const int tig  = lane & 3;

    const int x0 = blockIdx.x * 16, y0 = blockIdx.y * 16, b = blockIdx.z;

    auto stage = [&](int ch, int bsel) {
        __half* in_s = c4sm + bsel * C4_BUF_HALVES;
        __half* w_s  = in_s + 324 * 24;
        for (int t = tid; t < 324 * 4; t += 256) {
            int tpx = t >> 2, ci4 = t & 3;
            int yy = tpx / 18, xx = tpx - yy * 18;
            int iy = y0 - 1 + yy, ix = x0 - 1 + xx;
            bool valid = (iy >= 0 && iy < NH && ix >= 0 && ix < NW);
            size_t pix = valid ? ((size_t)(b * NH + iy) * NW + ix) : 0;
            const __half* src = g_mh + pix * 64 + ch * 16 + ci4 * 4;
            cp_async8z(in_s + tpx * 24 + ci4 * 4, src, valid);
        }
        const __half* wsrc_ch = w4h + ch * 1728;
        for (int t = tid; t < 216; t += 256)
            cp_async16(w_s + t * 8, wsrc_ch + t * 8);
    };

    float c[2][4];
    #pragma unroll
    for (int mt = 0; mt < 2; mt++)
        #pragma unroll
        for (int q = 0; q < 4; q++) c[mt][q] = 0.f;

    stage(0, 0);
    cp_commit();

    for (int ch = 0; ch < 4; ch++) {
        const int bsel = ch & 1;
        if (ch + 1 < 4) {
            stage(ch + 1, bsel ^ 1);
            cp_commit();
            cp_wait<1>();
        } else {
            cp_wait<0>();
        }
        __syncthreads();

        const __half* in_s = c4sm + bsel * C4_BUF_HALVES;
        const __half* w_s  = in_s + 324 * 24;

        #pragma unroll
        for (int tap = 0; tap < 9; tap++) {
            const int ky = tap / 3, kx = tap - 3 * (tap / 3);
            const __half* wb = w_s + (tap * 8 + gid) * 24 + 2 * tig;
            uint32_t b0 = *(const uint32_t*)(wb);
            uint32_t b1 = *(const uint32_t*)(wb + 8);
            #pragma unroll
            for (int mt = 0; mt < 2; mt++) {
                const int yl = 2 * w + mt;
                const __half* base = in_s + ((yl + ky) * 18 + kx) * 24 + 2 * tig;
                uint32_t a0 = *(const uint32_t*)(base + gid * 24);
                uint32_t a1 = *(const uint32_t*)(base + (gid + 8) * 24);
                uint32_t a2 = *(const uint32_t*)(base + gid * 24 + 8);
                uint32_t a3 = *(const uint32_t*)(base + (gid + 8) * 24 + 8);
                mma_f16(c[mt], a0, a1, a2, a3, b0, b1);
            }
        }
        __syncthreads();
    }

    if (tig < 2) {
        #pragma unroll
        for (int mt = 0; mt < 2; mt++) {
            const int y = y0 + 2 * w + mt;
            const int co0 = 2 * tig;
            const int x1 = x0 + gid, x2 = x0 + gid + 8;
            {
                int base = ((b*3 + co0) * NH + y) * NW;
                out[base + x1] = c[mt][0] + g_rgb[base + x1];
                out[base + x2] = c[mt][2] + g_rgb[base + x2];
            }
            if (co0 + 1 < 3) {
                int base = ((b*3 + co0 + 1) * NH + y) * NW;
                out[base + x1] = c[mt][1] + g_rgb[base + x1];
                out[base + x2] = c[mt][3] + g_rgb[base + x2];
            }
        }
    }
}

// ---------------------------------------------------------------------------
extern "C" void kernel_launch(void* const* d_in, const int* in_sizes, int n_in,
                              void* d_out, int out_size)
{
    const float* zbuf = (const float*)d_in[0];
    const float* ray  = (const float*)d_in[1];
    const float* w0 = (const float*)d_in[4];
    const float* b0 = (const float*)d_in[5];
    const float* w1 = (const float*)d_in[6];
    const float* b1 = (const float*)d_in[7];
    const float* w2 = (const float*)d_in[8];
    const float* b2 = (const float*)d_in[9];
    const float* k1 = (const float*)d_in[10];
    const float* k2 = (const float*)d_in[11];
    const float* k3 = (const float*)d_in[12];
    const float* k4 = (const float*)d_in[13];
    float* out = (float*)d_out;

    cudaFuncSetAttribute(mlp_kernel,
                         cudaFuncAttributeMaxDynamicSharedMemorySize, MLP_SMEM_BYTES);
    cudaFuncSetAttribute(conv13_kernel,
                         cudaFuncAttributeMaxDynamicSharedMemorySize, C13_SMEM_BYTES);
    cudaFuncSetAttribute(conv2_kernel,
                         cudaFuncAttributeMaxDynamicSharedMemorySize, C2_SMEM_BYTES);
    cudaFuncSetAttribute(conv4_kernel,
                         cudaFuncAttributeMaxDynamicSharedMemorySize, C4_SMEM_BYTES);

    const int prep_total = W1H_SZ + W2H_SZ + W3H_SZ + W4H_SZ + W1M_SZ + W2M_SZ;
    prep_weights<<<(prep_total + 255) / 256, 256>>>(k1, k2, k3, k4, w1, w2);

    mlp_kernel<<<(NB*NH*NW)/256, 512, MLP_SMEM_BYTES>>>(zbuf, ray, w0, b0, b1, b2);
    conv13_kernel<<<dim3(NW/16, NH/32, NB), 256, C13_SMEM_BYTES>>>(1, 0);
    conv2_kernel <<<dim3(16, 16, NB), 512, C2_SMEM_BYTES>>>();
    conv13_kernel<<<dim3(NW/16, NH/32, NB), 256, C13_SMEM_BYTES>>>(6, 1);
    conv4_kernel <<<dim3(NW/16, NH/16, NB), 256, C4_SMEM_BYTES>>>(out);
}